// round 4
// baseline (speedup 1.0000x reference)
#include <cuda_runtime.h>
#include <math.h>

// Problem constants
#define BB   16
#define CC   256
#define HH   64
#define WWD  64
#define HWP  (HH*WWD)          // 4096
#define NTOK (BB*HWP)          // 65536
#define KDIM 128
#define PP   256
#define BN_EPS 1e-5f

// Scratch (device globals: allocation-free per harness rules)
__device__ float g_k[PP*KDIM];
__device__ float g_v[PP*KDIM];
__device__ float g_q[(size_t)NTOK*KDIM];    // 32 MB, normalized q, token-major [n][d]
__device__ float g_ao[(size_t)NTOK*KDIM];   // 32 MB, attention output [n][d]
__device__ float g_y[(size_t)BB*CC*HWP];    // 64 MB, o-projected [b][c][hw]

// ---------------------------------------------------------------------------
// K1: k = l2norm(m @ k_w^T + k_b), v = m @ v_w^T + v_b     (tiny)
// grid = P blocks, 128 threads
// ---------------------------------------------------------------------------
__global__ __launch_bounds__(128) void kv_kernel(
    const float* __restrict__ m, const float* __restrict__ kw,
    const float* __restrict__ kb, const float* __restrict__ vw,
    const float* __restrict__ vb)
{
    __shared__ float mrow[KDIM];
    __shared__ float red[KDIM];
    int p = blockIdx.x;
    int d = threadIdx.x;
    mrow[d] = m[p*KDIM + d];
    __syncthreads();
    float kkv = kb[d], vvv = vb[d];
    #pragma unroll 4
    for (int j = 0; j < KDIM; j++) {
        float mj = mrow[j];
        kkv += mj * kw[d*KDIM + j];
        vvv += mj * vw[d*KDIM + j];
    }
    red[d] = kkv*kkv;
    __syncthreads();
    for (int s = 64; s > 0; s >>= 1) {
        if (d < s) red[d] += red[d+s];
        __syncthreads();
    }
    float scale = 1.f / fmaxf(sqrtf(red[0]), 1e-12f);
    g_k[p*KDIM + d] = kkv * scale;
    g_v[p*KDIM + d] = vvv;
}

// ---------------------------------------------------------------------------
// K2: q[n][d] = l2norm_d( x[b,:,hw] @ q_w^T + q_b )
// GEMM tile: M=64 pixels x N=128 dims, K=256 channels (chunks of 16).
// 256 threads, micro-tile 4 (pixels) x 8 (dims). tm=t>>4 rows, tn=t&15 cols.
// grid = (HW/64, B)
// ---------------------------------------------------------------------------
__global__ __launch_bounds__(256) void qproj_kernel(
    const float* __restrict__ x, const float* __restrict__ qw,
    const float* __restrict__ qb)
{
    __shared__ float As[16*68];    // [kk][m], padded
    __shared__ float Bs[16*132];   // [kk][d], padded
    int t = threadIdx.x;
    int b = blockIdx.y;
    int hw0 = blockIdx.x * 64;
    const float* xb = x + (size_t)b*CC*HWP;
    int tm = t >> 4, tn = t & 15;
    float acc[4][8] = {};

    for (int c0 = 0; c0 < CC; c0 += 16) {
        #pragma unroll
        for (int i = 0; i < 4; i++) {            // 16x64 A tile
            int idx = t + i*256;
            int kk = idx >> 6, mm = idx & 63;
            As[kk*68 + mm] = xb[(size_t)(c0+kk)*HWP + hw0 + mm];
        }
        #pragma unroll
        for (int i = 0; i < 8; i++) {            // 128x16 B tile (transpose on store)
            int idx = t + i*256;
            int dd = idx >> 4, kk = idx & 15;
            Bs[kk*132 + dd] = qw[dd*CC + c0 + kk];
        }
        __syncthreads();
        #pragma unroll
        for (int kk = 0; kk < 16; kk++) {
            float4 a  = *(const float4*)&As[kk*68 + tm*4];
            float4 b0 = *(const float4*)&Bs[kk*132 + tn*8];
            float4 b1 = *(const float4*)&Bs[kk*132 + tn*8 + 4];
            float av[4] = {a.x,a.y,a.z,a.w};
            float bv[8] = {b0.x,b0.y,b0.z,b0.w,b1.x,b1.y,b1.z,b1.w};
            #pragma unroll
            for (int i=0;i<4;i++) {
                #pragma unroll
                for (int j=0;j<8;j++) acc[i][j] += av[i]*bv[j];
            }
        }
        __syncthreads();
    }
    // bias
    #pragma unroll
    for (int j=0;j<8;j++) {
        float bb = qb[tn*8+j];
        #pragma unroll
        for (int i=0;i<4;i++) acc[i][j] += bb;
    }
    // row L2 norm: row owned by 16 lanes sharing tm (lanes 0-15 / 16-31)
    #pragma unroll
    for (int i=0;i<4;i++) {
        float ss = 0.f;
        #pragma unroll
        for (int j=0;j<8;j++) ss += acc[i][j]*acc[i][j];
        #pragma unroll
        for (int s=1;s<16;s<<=1) ss += __shfl_xor_sync(0xffffffffu, ss, s);
        float scale = 1.f / fmaxf(sqrtf(ss), 1e-12f);
        size_t n = (size_t)b*HWP + hw0 + tm*4 + i;
        *(float4*)&g_q[n*KDIM + tn*8] =
            make_float4(acc[i][0]*scale, acc[i][1]*scale, acc[i][2]*scale, acc[i][3]*scale);
        *(float4*)&g_q[n*KDIM + tn*8 + 4] =
            make_float4(acc[i][4]*scale, acc[i][5]*scale, acc[i][6]*scale, acc[i][7]*scale);
    }
}

// ---------------------------------------------------------------------------
// K3: fused attention per 64-token tile (single KV tile: P=256).
//   S = Q(64x128) @ K^T(128x256), softmax(clip(S/T)), O = A @ V(256x128)
// 256 threads: tm = t>>5 (8 tokens each), tn = t&31 (8 protos / 4 dims each).
// ---------------------------------------------------------------------------
#define ATTN_SMEM ((64*260 + 16*132)*4)

__global__ __launch_bounds__(256) void attn_kernel()
{
    extern __shared__ float sm[];
    float* As2 = sm;                 // 64 x 260 (attn weights), reuses GEMM1 staging
    float* Vs  = sm + 64*260;        // 16 x 132
    float* Qs  = sm;                 // 16 x 68   (GEMM1 only)
    float* Ks  = sm + 16*68;         // 16 x 264  (GEMM1 only)
    int t = threadIdx.x;
    size_t n0 = (size_t)blockIdx.x * 64;
    int tm = t >> 5;   // token group (8 tokens: tm*8..)
    int tn = t & 31;   // proto group (8 protos: tn*8..)

    float acc[8][8] = {};

    for (int d0 = 0; d0 < KDIM; d0 += 16) {
        #pragma unroll
        for (int i=0;i<4;i++) {                  // Qs[kk][m]
            int idx = t + i*256;
            int mm = idx >> 4, kk = idx & 15;
            Qs[kk*68 + mm] = g_q[(n0 + mm)*KDIM + d0 + kk];
        }
        #pragma unroll
        for (int i=0;i<16;i++) {                 // Ks[kk][p]
            int idx = t + i*256;
            int p = idx >> 4, kk = idx & 15;
            Ks[kk*264 + p] = g_k[p*KDIM + d0 + kk];
        }
        __syncthreads();
        #pragma unroll
        for (int kk=0; kk<16; kk++) {
            float4 a0 = *(const float4*)&Qs[kk*68 + tm*8];
            float4 a1 = *(const float4*)&Qs[kk*68 + tm*8 + 4];
            float4 b0 = *(const float4*)&Ks[kk*264 + tn*8];
            float4 b1 = *(const float4*)&Ks[kk*264 + tn*8 + 4];
            float av[8] = {a0.x,a0.y,a0.z,a0.w,a1.x,a1.y,a1.z,a1.w};
            float bv[8] = {b0.x,b0.y,b0.z,b0.w,b1.x,b1.y,b1.z,b1.w};
            #pragma unroll
            for (int i=0;i<8;i++) {
                #pragma unroll
                for (int j=0;j<8;j++) acc[i][j] += av[i]*bv[j];
            }
        }
        __syncthreads();
    }

    // softmax over 256 protos per row (spread across the warp's 32 lanes)
    const float invT = 1.0f/0.07f;
    #pragma unroll
    for (int i=0;i<8;i++) {
        float mx = -1e30f;
        #pragma unroll
        for (int j=0;j<8;j++) {
            float l = fminf(fmaxf(acc[i][j]*invT, -30.f), 30.f);
            acc[i][j] = l;
            mx = fmaxf(mx, l);
        }
        #pragma unroll
        for (int s=1;s<32;s<<=1) mx = fmaxf(mx, __shfl_xor_sync(0xffffffffu, mx, s));
        float sum = 0.f;
        #pragma unroll
        for (int j=0;j<8;j++) { float e = __expf(acc[i][j]-mx); acc[i][j]=e; sum+=e; }
        #pragma unroll
        for (int s=1;s<32;s<<=1) sum += __shfl_xor_sync(0xffffffffu, sum, s);
        float inv = 1.0f/sum;
        #pragma unroll
        for (int j=0;j<8;j++) acc[i][j] *= inv;
    }
    // stage attn weights
    #pragma unroll
    for (int i=0;i<8;i++) {
        *(float4*)&As2[(tm*8+i)*260 + tn*8] =
            make_float4(acc[i][0],acc[i][1],acc[i][2],acc[i][3]);
        *(float4*)&As2[(tm*8+i)*260 + tn*8 + 4] =
            make_float4(acc[i][4],acc[i][5],acc[i][6],acc[i][7]);
    }
    __syncthreads();

    // GEMM2: O[64][128] = A[64][256] @ V[256][128]; th = tn -> 4 dims each
    int th = tn;
    float oacc[8][4] = {};

    for (int p0=0; p0<PP; p0+=16) {
        #pragma unroll
        for (int i=0;i<8;i++) {                  // Vs[kk][d]
            int idx = t + i*256;
            int kk = idx >> 7, dd = idx & 127;
            Vs[kk*132 + dd] = g_v[(size_t)(p0+kk)*KDIM + dd];
        }
        __syncthreads();
        #pragma unroll
        for (int kk=0; kk<16; kk++) {
            float4 b = *(const float4*)&Vs[kk*132 + th*4];
            float bv[4]={b.x,b.y,b.z,b.w};
            #pragma unroll
            for (int i=0;i<8;i++) {
                float a = As2[(tm*8+i)*260 + p0 + kk];
                #pragma unroll
                for (int j=0;j<4;j++) oacc[i][j] += a*bv[j];
            }
        }
        __syncthreads();
    }
    #pragma unroll
    for (int i=0;i<8;i++) {
        *(float4*)&g_ao[(n0 + tm*8 + i)*KDIM + th*4] =
            make_float4(oacc[i][0],oacc[i][1],oacc[i][2],oacc[i][3]);
    }
}

// ---------------------------------------------------------------------------
// K4: y[b][c][hw] = attnout[b][hw][:] . o_w[c][:] + o_b[c]
// tile 64c x 64hw, K=128 in chunks of 16; micro 4x4. grid=(HW/64, C/64, B)
// ---------------------------------------------------------------------------
__global__ __launch_bounds__(256) void oproj_kernel(
    const float* __restrict__ ow, const float* __restrict__ ob)
{
    __shared__ float As[16*68];   // [kk][c]
    __shared__ float Bs[16*68];   // [kk][hw]
    int t = threadIdx.x;
    int hw0 = blockIdx.x * 64;
    int c0  = blockIdx.y * 64;
    int b   = blockIdx.z;
    int tc = t >> 4, th = t & 15;
    float acc[4][4] = {};

    for (int d0=0; d0<KDIM; d0+=16) {
        #pragma unroll
        for (int i=0;i<4;i++) {
            int idx = t + i*256;
            int rr = idx >> 4, kk = idx & 15;
            As[kk*68 + rr] = ow[(size_t)(c0+rr)*KDIM + d0 + kk];
            Bs[kk*68 + rr] = g_ao[((size_t)b*HWP + hw0 + rr)*KDIM + d0 + kk];
        }
        __syncthreads();
        #pragma unroll
        for (int kk=0; kk<16; kk++) {
            float4 a  = *(const float4*)&As[kk*68 + tc*4];
            float4 bq = *(const float4*)&Bs[kk*68 + th*4];
            float av[4]={a.x,a.y,a.z,a.w}, bv[4]={bq.x,bq.y,bq.z,bq.w};
            #pragma unroll
            for (int i=0;i<4;i++) {
                #pragma unroll
                for (int j=0;j<4;j++) acc[i][j] += av[i]*bv[j];
            }
        }
        __syncthreads();
    }
    #pragma unroll
    for (int i=0;i<4;i++) {
        int c = c0 + tc*4 + i;
        float bb = ob[c];
        *(float4*)&g_y[((size_t)b*CC + c)*HWP + hw0 + th*4] =
            make_float4(acc[i][0]+bb, acc[i][1]+bb, acc[i][2]+bb, acc[i][3]+bb);
    }
}

// ---------------------------------------------------------------------------
// K5: depthwise 3x3 (SAME) on y, BN1, exact GELU, residual, gamma, BN2.
// block (32,8), tile 32x8 with halo in smem. grid=(W/32, H/8, B*C)
// ---------------------------------------------------------------------------
__global__ __launch_bounds__(256) void final_kernel(
    const float* __restrict__ x, const float* __restrict__ dww,
    const float* __restrict__ bn1w, const float* __restrict__ bn1b,
    const float* __restrict__ bn2w, const float* __restrict__ bn2b,
    const float* __restrict__ gamma, float* __restrict__ out)
{
    __shared__ float tile[10][34];
    int bc = blockIdx.z;
    int c = bc & (CC-1);
    int h0 = blockIdx.y*8, w0 = blockIdx.x*32;
    int tx = threadIdx.x, ty = threadIdx.y;
    const float* yp = g_y + (size_t)bc*HWP;
    int tid = ty*32 + tx;
    for (int i = tid; i < 34*10; i += 256) {
        int yy = i / 34, xx = i - yy*34;
        int gh = h0 + yy - 1, gw = w0 + xx - 1;
        float v = 0.f;
        if (gh >= 0 && gh < HH && gw >= 0 && gw < WWD) v = yp[gh*WWD + gw];
        tile[yy][xx] = v;
    }
    __syncthreads();

    float kern[9];
    #pragma unroll
    for (int i=0;i<9;i++) kern[i] = dww[c*9 + i];
    float conv = 0.f;
    #pragma unroll
    for (int kh=0;kh<3;kh++) {
        #pragma unroll
        for (int kw=0;kw<3;kw++) conv += tile[ty+kh][tx+kw] * kern[kh*3+kw];
    }
    float inv = rsqrtf(1.f + BN_EPS);
    float z = conv * (bn1w[c]*inv) + bn1b[c];
    float gl = 0.5f * z * (1.f + erff(z * 0.70710678118654752f));
    float yv = tile[ty+1][tx+1];
    float ot = yv + gl;                           // out + local
    int hw = (h0+ty)*WWD + (w0+tx);
    float xv = x[(size_t)bc*HWP + hw];
    out[(size_t)bc*HWP + hw] = (xv + gamma[c]*ot) * (bn2w[c]*inv) + bn2b[c];
}

// ---------------------------------------------------------------------------
extern "C" void kernel_launch(void* const* d_in, const int* in_sizes, int n_in,
                              void* d_out, int out_size)
{
    (void)in_sizes; (void)n_in; (void)out_size;
    const float* x    = (const float*)d_in[0];
    const float* m    = (const float*)d_in[1];
    const float* qw   = (const float*)d_in[2];
    const float* qb   = (const float*)d_in[3];
    const float* kw   = (const float*)d_in[4];
    const float* kb   = (const float*)d_in[5];
    const float* vw   = (const float*)d_in[6];
    const float* vb   = (const float*)d_in[7];
    const float* ow   = (const float*)d_in[8];
    const float* ob   = (const float*)d_in[9];
    const float* dww  = (const float*)d_in[10];
    const float* bn1w = (const float*)d_in[11];
    const float* bn1b = (const float*)d_in[12];
    const float* bn2w = (const float*)d_in[13];
    const float* bn2b = (const float*)d_in[14];
    const float* gam  = (const float*)d_in[15];
    float* out = (float*)d_out;

    cudaFuncSetAttribute(attn_kernel, cudaFuncAttributeMaxDynamicSharedMemorySize, ATTN_SMEM);

    kv_kernel<<<PP, KDIM>>>(m, kw, kb, vw, vb);
    qproj_kernel<<<dim3(HWP/64, BB), 256>>>(x, qw, qb);
    attn_kernel<<<NTOK/64, 256, ATTN_SMEM>>>();
    oproj_kernel<<<dim3(HWP/64, CC/64, BB), 256>>>(ow, ob);
    final_kernel<<<dim3(WWD/32, HH/8, BB*CC), dim3(32,8)>>>(
        x, dww, bn1w, bn1b, bn2w, bn2b, gam, out);
}

// round 5
// speedup vs baseline: 2.3235x; 2.3235x over previous
#include <cuda_runtime.h>
#include <cuda_bf16.h>
#include <math.h>

typedef unsigned int u32;

// Problem constants
#define BB   16
#define CC   256
#define HH   64
#define WWD  64
#define HWP  (HH*WWD)          // 4096
#define NTOK (BB*HWP)          // 65536
#define KD   128
#define PP   256
#define BN_EPS 1e-5f

// Scratch (device globals: allocation-free per harness rules)
__device__ __nv_bfloat16 g_k[PP*KD];
__device__ __nv_bfloat16 g_v[PP*KD];
__device__ __nv_bfloat16 g_q[(size_t)NTOK*KD];    // 16 MB
__device__ __nv_bfloat16 g_ao[(size_t)NTOK*KD];   // 16 MB
__device__ __nv_bfloat16 g_y[(size_t)BB*CC*HWP];  // 32 MB

// ---------------------------------------------------------------------------
// MMA helpers (m16n8k16 bf16, fp32 accum)
// Fragment maps used (verified against PTX ISA layouts):
//  A  (row-major [m][k] smem):  ldmatrix.x4      addr = &S[m0+(lane%16)][k0+(lane/16)*8]
//  A  (col-major [k][m] smem):  ldmatrix.x4.trans addr = &S[k0+(lane%8)+(lane/16)*8][m0+((lane/8)%2)*8]
//  B  ([n][k] smem):            ldmatrix.x2      addr = &S[n0+(lane%8)][k0+(lane/8)*8]
//  B  ([k][n] smem):            ldmatrix.x2.trans addr = &S[k0+(lane%16)][n0]
//  C: c0,c1 = (row=lane/4, col=(lane%4)*2+{0,1}); c2,c3 = row+8
// ---------------------------------------------------------------------------
__device__ __forceinline__ u32 sm_u32(const void* p) {
    return (u32)__cvta_generic_to_shared(p);
}
__device__ __forceinline__ void ldsm_x4(u32* r, u32 a) {
    asm volatile("ldmatrix.sync.aligned.m8n8.x4.shared.b16 {%0,%1,%2,%3},[%4];"
                 : "=r"(r[0]),"=r"(r[1]),"=r"(r[2]),"=r"(r[3]) : "r"(a));
}
__device__ __forceinline__ void ldsm_x4t(u32* r, u32 a) {
    asm volatile("ldmatrix.sync.aligned.m8n8.x4.trans.shared.b16 {%0,%1,%2,%3},[%4];"
                 : "=r"(r[0]),"=r"(r[1]),"=r"(r[2]),"=r"(r[3]) : "r"(a));
}
__device__ __forceinline__ void ldsm_x2(u32* r, u32 a) {
    asm volatile("ldmatrix.sync.aligned.m8n8.x2.shared.b16 {%0,%1},[%2];"
                 : "=r"(r[0]),"=r"(r[1]) : "r"(a));
}
__device__ __forceinline__ void ldsm_x2t(u32* r, u32 a) {
    asm volatile("ldmatrix.sync.aligned.m8n8.x2.trans.shared.b16 {%0,%1},[%2];"
                 : "=r"(r[0]),"=r"(r[1]) : "r"(a));
}
__device__ __forceinline__ void mma16816(float* d, const u32* a, const u32* b) {
    asm volatile("mma.sync.aligned.m16n8k16.row.col.f32.bf16.bf16.f32 "
                 "{%0,%1,%2,%3},{%4,%5,%6,%7},{%8,%9},{%0,%1,%2,%3};"
                 : "+f"(d[0]),"+f"(d[1]),"+f"(d[2]),"+f"(d[3])
                 : "r"(a[0]),"r"(a[1]),"r"(a[2]),"r"(a[3]),"r"(b[0]),"r"(b[1]));
}
__device__ __forceinline__ void st_bf2(__nv_bfloat16* p, float a, float b) {
    *(__nv_bfloat162*)p = __floats2bfloat162_rn(a, b);
}

// ---------------------------------------------------------------------------
// K1: k = l2norm(m @ k_w^T + k_b), v = m @ v_w^T + v_b  (tiny, fp32 math)
// ---------------------------------------------------------------------------
__global__ __launch_bounds__(128) void kv_kernel(
    const float* __restrict__ m, const float* __restrict__ kw,
    const float* __restrict__ kb, const float* __restrict__ vw,
    const float* __restrict__ vb)
{
    __shared__ float mrow[KD];
    __shared__ float red[KD];
    int p = blockIdx.x;
    int d = threadIdx.x;
    mrow[d] = m[p*KD + d];
    __syncthreads();
    float kkv = kb[d], vvv = vb[d];
    #pragma unroll 4
    for (int j = 0; j < KD; j++) {
        float mj = mrow[j];
        kkv += mj * kw[d*KD + j];
        vvv += mj * vw[d*KD + j];
    }
    red[d] = kkv*kkv;
    __syncthreads();
    for (int s = 64; s > 0; s >>= 1) {
        if (d < s) red[d] += red[d+s];
        __syncthreads();
    }
    float scale = 1.f / fmaxf(sqrtf(red[0]), 1e-12f);
    g_k[p*KD + d] = __float2bfloat16(kkv * scale);
    g_v[p*KD + d] = __float2bfloat16(vvv);
}

// ---------------------------------------------------------------------------
// K2: qproj + L2 norm. Tile: 128 pixels x 128 dims, K=256 channels.
// smem: Xs[k=c][m=pix] (natural from x), Qw[n=d][k=c] (natural from qw).
// 8 warps, warp tile 16m x 128n -> each warp owns whole rows for the norm.
// ---------------------------------------------------------------------------
#define XS_LD 136
#define QW_LD 264
#define QP_SMEM ((256*XS_LD + 128*QW_LD)*2)   // 69632 + 67584 = 137216 B

__global__ __launch_bounds__(256,1) void qproj_mma(
    const float* __restrict__ x, const float* __restrict__ qw,
    const float* __restrict__ qb)
{
    extern __shared__ __nv_bfloat16 smq[];
    __nv_bfloat16* Xs = smq;                 // [256][XS_LD]
    __nv_bfloat16* Qw = smq + 256*XS_LD;     // [128][QW_LD]
    int tid = threadIdx.x;
    int b = blockIdx.y, hw0 = blockIdx.x*128;
    const float* xb = x + (size_t)b*CC*HWP;

    for (int i = tid; i < 256*32; i += 256) {           // X: 256 rows x 128
        int c = i >> 5, m4 = (i & 31) << 2;
        float4 v = *(const float4*)&xb[(size_t)c*HWP + hw0 + m4];
        __nv_bfloat162* d2 = (__nv_bfloat162*)&Xs[c*XS_LD + m4];
        d2[0] = __floats2bfloat162_rn(v.x, v.y);
        d2[1] = __floats2bfloat162_rn(v.z, v.w);
    }
    for (int i = tid; i < 128*64; i += 256) {           // QW: 128 rows x 256
        int d = i >> 6, c4 = (i & 63) << 2;
        float4 v = *(const float4*)&qw[d*CC + c4];
        __nv_bfloat162* d2 = (__nv_bfloat162*)&Qw[d*QW_LD + c4];
        d2[0] = __floats2bfloat162_rn(v.x, v.y);
        d2[1] = __floats2bfloat162_rn(v.z, v.w);
    }
    __syncthreads();

    int warp = tid >> 5, lane = tid & 31;
    int m_w = warp*16;
    float acc[16][4];
    #pragma unroll
    for (int nt = 0; nt < 16; nt++) { acc[nt][0]=acc[nt][1]=acc[nt][2]=acc[nt][3]=0.f; }

    u32 a_base = sm_u32(&Xs[((lane&7) + ((lane>>4)<<3))*XS_LD + m_w + ((lane>>3)&1)*8]);
    u32 b_base = sm_u32(&Qw[(lane&7)*QW_LD + ((lane>>3)&1)*8]);
    #pragma unroll
    for (int ks = 0; ks < 16; ks++) {
        u32 a[4];
        ldsm_x4t(a, a_base + ks*16*XS_LD*2);
        #pragma unroll
        for (int nt = 0; nt < 16; nt++) {
            u32 bf[2];
            ldsm_x2(bf, b_base + (nt*8*QW_LD + ks*16)*2);
            mma16816(acc[nt], a, bf);
        }
    }
    // bias + L2 norm (row spread over lane quads 0..3) + bf16 store
    int r = lane >> 2, col0 = (lane & 3)*2;
    float slo = 0.f, shi = 0.f;
    #pragma unroll
    for (int nt = 0; nt < 16; nt++) {
        float b0 = __ldg(&qb[nt*8+col0]), b1 = __ldg(&qb[nt*8+col0+1]);
        acc[nt][0] += b0; acc[nt][1] += b1; acc[nt][2] += b0; acc[nt][3] += b1;
        slo += acc[nt][0]*acc[nt][0] + acc[nt][1]*acc[nt][1];
        shi += acc[nt][2]*acc[nt][2] + acc[nt][3]*acc[nt][3];
    }
    slo += __shfl_xor_sync(~0u, slo, 1); slo += __shfl_xor_sync(~0u, slo, 2);
    shi += __shfl_xor_sync(~0u, shi, 1); shi += __shfl_xor_sync(~0u, shi, 2);
    float s_lo = 1.f/fmaxf(sqrtf(slo), 1e-12f);
    float s_hi = 1.f/fmaxf(sqrtf(shi), 1e-12f);
    size_t tok_lo = (size_t)b*HWP + hw0 + m_w + r;
    size_t tok_hi = tok_lo + 8;
    #pragma unroll
    for (int nt = 0; nt < 16; nt++) {
        st_bf2(&g_q[tok_lo*KD + nt*8 + col0], acc[nt][0]*s_lo, acc[nt][1]*s_lo);
        st_bf2(&g_q[tok_hi*KD + nt*8 + col0], acc[nt][2]*s_hi, acc[nt][3]*s_hi);
    }
}

// ---------------------------------------------------------------------------
// K3: fused attention, 128 tokens per CTA (single KV tile, P=256).
// Phase1: S = Q@K^T (warp tile 16x256) -> clipped softmax in registers
// Phase2: O = P@V (P bf16 in smem, V overlays dead Q/K smem region)
// ---------------------------------------------------------------------------
#define PS_LD 264
#define AT_SMEM ((256*XS_LD + 128*XS_LD + 128*PS_LD)*2)   // 172032 B

__global__ __launch_bounds__(256,1) void attn_mma()
{
    extern __shared__ __nv_bfloat16 sma[];
    __nv_bfloat16* Ks = sma;                               // [256][136]
    __nv_bfloat16* Qs = sma + 256*XS_LD;                   // [128][136]
    __nv_bfloat16* Ps = sma + 256*XS_LD + 128*XS_LD;       // [128][264]
    __nv_bfloat16* Vs = sma;                               // overlays Ks/Qs (phase2)
    int tid = threadIdx.x;
    size_t n0 = (size_t)blockIdx.x * 128;
    int warp = tid >> 5, lane = tid & 31;
    int m_w = warp*16;
    int r = lane >> 2, col0 = (lane & 3)*2;

    for (int i = tid; i < 128*16; i += 256) {
        int m = i >> 4, d8 = (i & 15) << 3;
        *(uint4*)&Qs[m*XS_LD + d8] = *(const uint4*)&g_q[(n0+m)*KD + d8];
    }
    for (int i = tid; i < 256*16; i += 256) {
        int p = i >> 4, d8 = (i & 15) << 3;
        *(uint4*)&Ks[p*XS_LD + d8] = *(const uint4*)&g_k[p*KD + d8];
    }
    __syncthreads();

    {   // Phase 1: S + softmax
        float acc[32][4];
        #pragma unroll
        for (int nt = 0; nt < 32; nt++) { acc[nt][0]=acc[nt][1]=acc[nt][2]=acc[nt][3]=0.f; }
        u32 a_base = sm_u32(&Qs[(m_w + (lane&15))*XS_LD + ((lane>>4)&1)*8]);
        u32 b_base = sm_u32(&Ks[(lane&7)*XS_LD + ((lane>>3)&1)*8]);
        #pragma unroll
        for (int ks = 0; ks < 8; ks++) {
            u32 a[4];
            ldsm_x4(a, a_base + ks*16*2);
            #pragma unroll
            for (int nt = 0; nt < 32; nt++) {
                u32 bf[2];
                ldsm_x2(bf, b_base + (nt*8*XS_LD + ks*16)*2);
                mma16816(acc[nt], a, bf);
            }
        }
        const float invT = 1.0f/0.07f;
        float mlo = -1e30f, mhi = -1e30f;
        #pragma unroll
        for (int nt = 0; nt < 32; nt++) {
            #pragma unroll
            for (int e = 0; e < 2; e++) {
                float l = fminf(fmaxf(acc[nt][e]*invT, -30.f), 30.f);
                acc[nt][e] = l; mlo = fmaxf(mlo, l);
                float h = fminf(fmaxf(acc[nt][2+e]*invT, -30.f), 30.f);
                acc[nt][2+e] = h; mhi = fmaxf(mhi, h);
            }
        }
        mlo = fmaxf(mlo, __shfl_xor_sync(~0u, mlo, 1));
        mlo = fmaxf(mlo, __shfl_xor_sync(~0u, mlo, 2));
        mhi = fmaxf(mhi, __shfl_xor_sync(~0u, mhi, 1));
        mhi = fmaxf(mhi, __shfl_xor_sync(~0u, mhi, 2));
        float slo = 0.f, shi = 0.f;
        #pragma unroll
        for (int nt = 0; nt < 32; nt++) {
            #pragma unroll
            for (int e = 0; e < 2; e++) {
                float pl = __expf(acc[nt][e] - mlo);   acc[nt][e] = pl;   slo += pl;
                float ph = __expf(acc[nt][2+e] - mhi); acc[nt][2+e] = ph; shi += ph;
            }
        }
        slo += __shfl_xor_sync(~0u, slo, 1); slo += __shfl_xor_sync(~0u, slo, 2);
        shi += __shfl_xor_sync(~0u, shi, 1); shi += __shfl_xor_sync(~0u, shi, 2);
        float ilo = 1.f/slo, ihi = 1.f/shi;
        #pragma unroll
        for (int nt = 0; nt < 32; nt++) {
            st_bf2(&Ps[(m_w+r)*PS_LD + nt*8 + col0],   acc[nt][0]*ilo, acc[nt][1]*ilo);
            st_bf2(&Ps[(m_w+r+8)*PS_LD + nt*8 + col0], acc[nt][2]*ihi, acc[nt][3]*ihi);
        }
    }
    __syncthreads();                    // everyone done with Ks/Qs, Ps complete
    for (int i = tid; i < 256*16; i += 256) {
        int p = i >> 4, d8 = (i & 15) << 3;
        *(uint4*)&Vs[p*XS_LD + d8] = *(const uint4*)&g_v[p*KD + d8];
    }
    __syncthreads();

    {   // Phase 2: O = P @ V
        float acc[16][4];
        #pragma unroll
        for (int nt = 0; nt < 16; nt++) { acc[nt][0]=acc[nt][1]=acc[nt][2]=acc[nt][3]=0.f; }
        u32 a_base = sm_u32(&Ps[(m_w + (lane&15))*PS_LD + ((lane>>4)&1)*8]);
        u32 b_base = sm_u32(&Vs[(lane&15)*XS_LD]);
        #pragma unroll
        for (int ks = 0; ks < 16; ks++) {
            u32 a[4];
            ldsm_x4(a, a_base + ks*16*2);
            #pragma unroll
            for (int nt = 0; nt < 16; nt++) {
                u32 bf[2];
                ldsm_x2t(bf, b_base + (ks*16*XS_LD + nt*8)*2);
                mma16816(acc[nt], a, bf);
            }
        }
        size_t tok_lo = n0 + m_w + r, tok_hi = tok_lo + 8;
        #pragma unroll
        for (int nt = 0; nt < 16; nt++) {
            st_bf2(&g_ao[tok_lo*KD + nt*8 + col0], acc[nt][0], acc[nt][1]);
            st_bf2(&g_ao[tok_hi*KD + nt*8 + col0], acc[nt][2], acc[nt][3]);
        }
    }
}

// ---------------------------------------------------------------------------
// K4: y[c][hw] = ow[c][:] . ao[hw][:] + ob[c].  Tile 128c x 128hw, K=128.
// ---------------------------------------------------------------------------
#define OP_SMEM ((128*XS_LD + 128*XS_LD)*2)   // 69632 B

__global__ __launch_bounds__(256,2) void oproj_mma(
    const float* __restrict__ ow, const float* __restrict__ ob)
{
    extern __shared__ __nv_bfloat16 smo[];
    __nv_bfloat16* OWs = smo;                 // [128][136]  (rows c, cols d)
    __nv_bfloat16* AOs = smo + 128*XS_LD;     // [128][136]  (rows hw, cols d)
    int tid = threadIdx.x;
    int c0 = blockIdx.x*128, hw0 = blockIdx.y*128, b = blockIdx.z;

    for (int i = tid; i < 128*32; i += 256) {
        int c = i >> 5, d4 = (i & 31) << 2;
        float4 v = *(const float4*)&ow[(size_t)(c0+c)*KD + d4];
        __nv_bfloat162* d2 = (__nv_bfloat162*)&OWs[c*XS_LD + d4];
        d2[0] = __floats2bfloat162_rn(v.x, v.y);
        d2[1] = __floats2bfloat162_rn(v.z, v.w);
    }
    for (int i = tid; i < 128*16; i += 256) {
        int hw = i >> 4, d8 = (i & 15) << 3;
        *(uint4*)&AOs[hw*XS_LD + d8] = *(const uint4*)&g_ao[((size_t)b*HWP + hw0 + hw)*KD + d8];
    }
    __syncthreads();

    int warp = tid >> 5, lane = tid & 31;
    int c_w = warp*16;
    float acc[16][4];
    #pragma unroll
    for (int nt = 0; nt < 16; nt++) { acc[nt][0]=acc[nt][1]=acc[nt][2]=acc[nt][3]=0.f; }
    u32 a_base = sm_u32(&OWs[(c_w + (lane&15))*XS_LD + ((lane>>4)&1)*8]);
    u32 b_base = sm_u32(&AOs[(lane&7)*XS_LD + ((lane>>3)&1)*8]);
    #pragma unroll
    for (int ks = 0; ks < 8; ks++) {
        u32 a[4];
        ldsm_x4(a, a_base + ks*16*2);
        #pragma unroll
        for (int nt = 0; nt < 16; nt++) {
            u32 bf[2];
            ldsm_x2(bf, b_base + (nt*8*XS_LD + ks*16)*2);
            mma16816(acc[nt], a, bf);
        }
    }
    int r = lane >> 2, col0 = (lane & 3)*2;
    int c_lo = c0 + c_w + r, c_hi = c_lo + 8;
    float b_lo = __ldg(&ob[c_lo]), b_hi = __ldg(&ob[c_hi]);
    size_t base_lo = ((size_t)b*CC + c_lo)*HWP + hw0;
    size_t base_hi = ((size_t)b*CC + c_hi)*HWP + hw0;
    #pragma unroll
    for (int nt = 0; nt < 16; nt++) {
        st_bf2(&g_y[base_lo + nt*8 + col0], acc[nt][0]+b_lo, acc[nt][1]+b_lo);
        st_bf2(&g_y[base_hi + nt*8 + col0], acc[nt][2]+b_hi, acc[nt][3]+b_hi);
    }
}

// ---------------------------------------------------------------------------
// K5: depthwise 3x3 (SAME) on y (bf16), BN1, exact GELU, residual, gamma, BN2.
// ---------------------------------------------------------------------------
__global__ __launch_bounds__(256) void final_kernel(
    const float* __restrict__ x, const float* __restrict__ dww,
    const float* __restrict__ bn1w, const float* __restrict__ bn1b,
    const float* __restrict__ bn2w, const float* __restrict__ bn2b,
    const float* __restrict__ gamma, float* __restrict__ out)
{
    __shared__ float tile[10][34];
    int bc = blockIdx.z;
    int c = bc & (CC-1);
    int h0 = blockIdx.y*8, w0 = blockIdx.x*32;
    int tx = threadIdx.x, ty = threadIdx.y;
    const __nv_bfloat16* yp = g_y + (size_t)bc*HWP;
    int tid = ty*32 + tx;
    for (int i = tid; i < 34*10; i += 256) {
        int yy = i / 34, xx = i - yy*34;
        int gh = h0 + yy - 1, gw = w0 + xx - 1;
        float v = 0.f;
        if (gh >= 0 && gh < HH && gw >= 0 && gw < WWD)
            v = __bfloat162float(yp[gh*WWD + gw]);
        tile[yy][xx] = v;
    }
    __syncthreads();

    float kern[9];
    #pragma unroll
    for (int i = 0; i < 9; i++) kern[i] = dww[c*9 + i];
    float conv = 0.f;
    #pragma unroll
    for (int kh = 0; kh < 3; kh++) {
        #pragma unroll
        for (int kw = 0; kw < 3; kw++) conv += tile[ty+kh][tx+kw] * kern[kh*3+kw];
    }
    float inv = rsqrtf(1.f + BN_EPS);
    float z = conv * (bn1w[c]*inv) + bn1b[c];
    float gl = 0.5f * z * (1.f + erff(z * 0.70710678118654752f));
    float yv = tile[ty+1][tx+1];
    float ot = yv + gl;                           // out + local
    int hw = (h0+ty)*WWD + (w0+tx);
    float xv = x[(size_t)bc*HWP + hw];
    out[(size_t)bc*HWP + hw] = (xv + gamma[c]*ot) * (bn2w[c]*inv) + bn2b[c];
}

// ---------------------------------------------------------------------------
extern "C" void kernel_launch(void* const* d_in, const int* in_sizes, int n_in,
                              void* d_out, int out_size)
{
    (void)in_sizes; (void)n_in; (void)out_size;
    const float* x    = (const float*)d_in[0];
    const float* m    = (const float*)d_in[1];
    const float* qw   = (const float*)d_in[2];
    const float* qb   = (const float*)d_in[3];
    const float* kw   = (const float*)d_in[4];
    const float* kb   = (const float*)d_in[5];
    const float* vw   = (const float*)d_in[6];
    const float* vb   = (const float*)d_in[7];
    const float* ow   = (const float*)d_in[8];
    const float* ob   = (const float*)d_in[9];
    const float* dww  = (const float*)d_in[10];
    const float* bn1w = (const float*)d_in[11];
    const float* bn1b = (const float*)d_in[12];
    const float* bn2w = (const float*)d_in[13];
    const float* bn2b = (const float*)d_in[14];
    const float* gam  = (const float*)d_in[15];
    float* out = (float*)d_out;

    cudaFuncSetAttribute(qproj_mma, cudaFuncAttributeMaxDynamicSharedMemorySize, QP_SMEM);
    cudaFuncSetAttribute(attn_mma,  cudaFuncAttributeMaxDynamicSharedMemorySize, AT_SMEM);
    cudaFuncSetAttribute(oproj_mma, cudaFuncAttributeMaxDynamicSharedMemorySize, OP_SMEM);

    kv_kernel<<<PP, KD>>>(m, kw, kb, vw, vb);
    qproj_mma<<<dim3(HWP/128, BB), 256, QP_SMEM>>>(x, qw, qb);
    attn_mma<<<NTOK/128, 256, AT_SMEM>>>();
    oproj_mma<<<dim3(CC/128, HWP/128, BB), 256, OP_SMEM>>>(ow, ob);
    final_kernel<<<dim3(WWD/32, HH/8, BB*CC), dim3(32,8)>>>(
        x, dww, bn1w, bn1b, bn2w, bn2b, gam, out);
}

// round 6
// speedup vs baseline: 2.6218x; 1.1283x over previous
#include <cuda_runtime.h>
#include <cuda_bf16.h>
#include <math.h>

typedef unsigned int u32;

// Problem constants
#define BB   16
#define CC   256
#define HH   64
#define WWD  64
#define HWP  (HH*WWD)          // 4096
#define NTOK (BB*HWP)          // 65536
#define KD   128
#define PP   256
#define BN_EPS 1e-5f

// Scratch (device globals: allocation-free per harness rules)
__device__ __align__(256) __nv_bfloat16 g_k[PP*KD];
__device__ __align__(256) __nv_bfloat16 g_v[PP*KD];
__device__ __align__(256) __nv_bfloat16 g_q[(size_t)NTOK*KD];    // 16 MB
__device__ __align__(256) __nv_bfloat16 g_ao[(size_t)NTOK*KD];   // 16 MB
__device__ __align__(256) __nv_bfloat16 g_y[(size_t)BB*CC*HWP];  // 32 MB

// ---------------------------------------------------------------------------
// MMA / ldmatrix helpers (m16n8k16 bf16, fp32 accum)
// ---------------------------------------------------------------------------
__device__ __forceinline__ u32 sm_u32(const void* p) {
    return (u32)__cvta_generic_to_shared(p);
}
__device__ __forceinline__ void ldsm_x4(u32* r, u32 a) {
    asm volatile("ldmatrix.sync.aligned.m8n8.x4.shared.b16 {%0,%1,%2,%3},[%4];"
                 : "=r"(r[0]),"=r"(r[1]),"=r"(r[2]),"=r"(r[3]) : "r"(a));
}
__device__ __forceinline__ void ldsm_x4t(u32* r, u32 a) {
    asm volatile("ldmatrix.sync.aligned.m8n8.x4.trans.shared.b16 {%0,%1,%2,%3},[%4];"
                 : "=r"(r[0]),"=r"(r[1]),"=r"(r[2]),"=r"(r[3]) : "r"(a));
}
__device__ __forceinline__ void mma16816(float* d, const u32* a, const u32* b) {
    asm volatile("mma.sync.aligned.m16n8k16.row.col.f32.bf16.bf16.f32 "
                 "{%0,%1,%2,%3},{%4,%5,%6,%7},{%8,%9},{%0,%1,%2,%3};"
                 : "+f"(d[0]),"+f"(d[1]),"+f"(d[2]),"+f"(d[3])
                 : "r"(a[0]),"r"(a[1]),"r"(a[2]),"r"(a[3]),"r"(b[0]),"r"(b[1]));
}
__device__ __forceinline__ void st_bf2(__nv_bfloat16* p, float a, float b) {
    *(__nv_bfloat162*)p = __floats2bfloat162_rn(a, b);
}
__device__ __forceinline__ u32 pack_bf2(float a, float b) {
    __nv_bfloat162 t = __floats2bfloat162_rn(a, b);
    return *(u32*)&t;
}
__device__ __forceinline__ void cpa16(void* dst, const void* src) {
    u32 d = sm_u32(dst);
    asm volatile("cp.async.cg.shared.global [%0], [%1], 16;" :: "r"(d), "l"(src));
}
__device__ __forceinline__ void cpa_commit() {
    asm volatile("cp.async.commit_group;");
}
template<int N> __device__ __forceinline__ void cpa_wait() {
    asm volatile("cp.async.wait_group %0;" :: "n"(N));
}

// ---------------------------------------------------------------------------
// K1: k = l2norm(m @ k_w^T + k_b), v = m @ v_w^T + v_b  (tiny, fp32 math)
// ---------------------------------------------------------------------------
__global__ __launch_bounds__(128) void kv_kernel(
    const float* __restrict__ m, const float* __restrict__ kw,
    const float* __restrict__ kb, const float* __restrict__ vw,
    const float* __restrict__ vb)
{
    __shared__ float mrow[KD];
    __shared__ float red[KD];
    int p = blockIdx.x;
    int d = threadIdx.x;
    mrow[d] = m[p*KD + d];
    __syncthreads();
    float kkv = kb[d], vvv = vb[d];
    #pragma unroll 4
    for (int j = 0; j < KD; j++) {
        float mj = mrow[j];
        kkv += mj * kw[d*KD + j];
        vvv += mj * vw[d*KD + j];
    }
    red[d] = kkv*kkv;
    __syncthreads();
    for (int s = 64; s > 0; s >>= 1) {
        if (d < s) red[d] += red[d+s];
        __syncthreads();
    }
    float scale = 1.f / fmaxf(sqrtf(red[0]), 1e-12f);
    g_k[p*KD + d] = __float2bfloat16(kkv * scale);
    g_v[p*KD + d] = __float2bfloat16(vvv);
}

// ---------------------------------------------------------------------------
// K2: qproj + L2 norm. Tile: 128 pixels x 128 dims, K=256 channels.
// Xs[c][m] col-major A (x4t), Qw[d][c] = [n][k] B (x4).
// ---------------------------------------------------------------------------
#define XS_LD 136
#define QW_LD 264
#define QP_SMEM ((256*XS_LD + 128*QW_LD)*2)

__global__ __launch_bounds__(256,1) void qproj_mma(
    const float* __restrict__ x, const float* __restrict__ qw,
    const float* __restrict__ qb)
{
    extern __shared__ __nv_bfloat16 smq[];
    __nv_bfloat16* Xs = smq;                 // [256][XS_LD]
    __nv_bfloat16* Qw = smq + 256*XS_LD;     // [128][QW_LD]
    int tid = threadIdx.x;
    int b = blockIdx.y, hw0 = blockIdx.x*128;
    const float* xb = x + (size_t)b*CC*HWP;

    for (int i = tid; i < 256*32; i += 256) {           // X: 256c x 128m
        int c = i >> 5, m4 = (i & 31) << 2;
        float4 v = *(const float4*)&xb[(size_t)c*HWP + hw0 + m4];
        __nv_bfloat162* d2 = (__nv_bfloat162*)&Xs[c*XS_LD + m4];
        d2[0] = __floats2bfloat162_rn(v.x, v.y);
        d2[1] = __floats2bfloat162_rn(v.z, v.w);
    }
    for (int i = tid; i < 128*64; i += 256) {           // QW: 128d x 256c
        int d = i >> 6, c4 = (i & 63) << 2;
        float4 v = *(const float4*)&qw[d*CC + c4];
        __nv_bfloat162* d2 = (__nv_bfloat162*)&Qw[d*QW_LD + c4];
        d2[0] = __floats2bfloat162_rn(v.x, v.y);
        d2[1] = __floats2bfloat162_rn(v.z, v.w);
    }
    __syncthreads();

    int warp = tid >> 5, lane = tid & 31;
    int m_w = warp*16;
    float acc[16][4];
    #pragma unroll
    for (int nt = 0; nt < 16; nt++) { acc[nt][0]=acc[nt][1]=acc[nt][2]=acc[nt][3]=0.f; }

    u32 a_base = sm_u32(&Xs[((lane&7) + ((lane>>4)<<3))*XS_LD + m_w + ((lane>>3)&1)*8]);
    u32 b_base = sm_u32(&Qw[((lane&7) + ((lane>>4)<<3))*QW_LD + ((lane>>3)&1)*8]);
    #pragma unroll
    for (int ks = 0; ks < 16; ks++) {
        u32 a[4];
        ldsm_x4t(a, a_base + ks*16*XS_LD*2);
        #pragma unroll
        for (int ntp = 0; ntp < 8; ntp++) {
            u32 bf[4];
            ldsm_x4(bf, b_base + (ntp*16*QW_LD + ks*16)*2);
            mma16816(acc[2*ntp],   a, bf);
            mma16816(acc[2*ntp+1], a, bf+2);
        }
    }
    // bias + L2 norm (row spread over lane quads) + bf16 store
    int r = lane >> 2, col0 = (lane & 3)*2;
    float slo = 0.f, shi = 0.f;
    #pragma unroll
    for (int nt = 0; nt < 16; nt++) {
        float b0 = __ldg(&qb[nt*8+col0]), b1 = __ldg(&qb[nt*8+col0+1]);
        acc[nt][0] += b0; acc[nt][1] += b1; acc[nt][2] += b0; acc[nt][3] += b1;
        slo += acc[nt][0]*acc[nt][0] + acc[nt][1]*acc[nt][1];
        shi += acc[nt][2]*acc[nt][2] + acc[nt][3]*acc[nt][3];
    }
    slo += __shfl_xor_sync(~0u, slo, 1); slo += __shfl_xor_sync(~0u, slo, 2);
    shi += __shfl_xor_sync(~0u, shi, 1); shi += __shfl_xor_sync(~0u, shi, 2);
    float s_lo = 1.f/fmaxf(sqrtf(slo), 1e-12f);
    float s_hi = 1.f/fmaxf(sqrtf(shi), 1e-12f);
    size_t tok_lo = (size_t)b*HWP + hw0 + m_w + r;
    size_t tok_hi = tok_lo + 8;
    #pragma unroll
    for (int nt = 0; nt < 16; nt++) {
        st_bf2(&g_q[tok_lo*KD + nt*8 + col0], acc[nt][0]*s_lo, acc[nt][1]*s_lo);
        st_bf2(&g_q[tok_hi*KD + nt*8 + col0], acc[nt][2]*s_hi, acc[nt][3]*s_hi);
    }
}

// ---------------------------------------------------------------------------
// K3: fused attention, 128 tokens/CTA. S=Q@K^T -> softmax in regs ->
// P stays in registers (C-frag == A-frag layout) -> O=P@V.
// V prefetched via its own cp.async group, overlapped with phase 1.
// ---------------------------------------------------------------------------
#define AT_SMEM ((256*XS_LD + 128*XS_LD + 256*XS_LD)*2)   // 174080 B

__global__ __launch_bounds__(256,1) void attn_mma()
{
    extern __shared__ __nv_bfloat16 sma[];
    __nv_bfloat16* Ks = sma;                               // [256][136]
    __nv_bfloat16* Qs = sma + 256*XS_LD;                   // [128][136]
    __nv_bfloat16* Vs = sma + 256*XS_LD + 128*XS_LD;       // [256][136]
    int tid = threadIdx.x;
    size_t n0 = (size_t)blockIdx.x * 128;
    int warp = tid >> 5, lane = tid & 31;
    int m_w = warp*16;
    int r = lane >> 2, col0 = (lane & 3)*2;

    for (int i = tid; i < 128*16; i += 256) {
        int m = i >> 4, d8 = (i & 15) << 3;
        cpa16(&Qs[m*XS_LD + d8], &g_q[(n0+m)*KD + d8]);
    }
    for (int i = tid; i < 256*16; i += 256) {
        int p = i >> 4, d8 = (i & 15) << 3;
        cpa16(&Ks[p*XS_LD + d8], &g_k[p*KD + d8]);
    }
    cpa_commit();                      // group A: Q+K
    for (int i = tid; i < 256*16; i += 256) {
        int p = i >> 4, d8 = (i & 15) << 3;
        cpa16(&Vs[p*XS_LD + d8], &g_v[p*KD + d8]);
    }
    cpa_commit();                      // group B: V (overlaps phase 1)
    cpa_wait<1>();                     // Q+K ready
    __syncthreads();

    float acc[32][4];
    #pragma unroll
    for (int nt = 0; nt < 32; nt++) { acc[nt][0]=acc[nt][1]=acc[nt][2]=acc[nt][3]=0.f; }
    {   // Phase 1: S = Q @ K^T
        u32 a_base = sm_u32(&Qs[(m_w + (lane&15))*XS_LD + ((lane>>4)&1)*8]);
        u32 b_base = sm_u32(&Ks[((lane&7) + ((lane>>4)<<3))*XS_LD + ((lane>>3)&1)*8]);
        #pragma unroll
        for (int ks = 0; ks < 8; ks++) {
            u32 a[4];
            ldsm_x4(a, a_base + ks*16*2);
            #pragma unroll
            for (int ntp = 0; ntp < 16; ntp++) {
                u32 bf[4];
                ldsm_x4(bf, b_base + (ntp*16*XS_LD + ks*16)*2);
                mma16816(acc[2*ntp],   a, bf);
                mma16816(acc[2*ntp+1], a, bf+2);
            }
        }
    }
    // softmax over 256 protos (rows r and r+8, spread over lane quads)
    const float invT = 1.0f/0.07f;
    float mlo = -1e30f, mhi = -1e30f;
    #pragma unroll
    for (int nt = 0; nt < 32; nt++) {
        #pragma unroll
        for (int e = 0; e < 2; e++) {
            float l = fminf(fmaxf(acc[nt][e]*invT, -30.f), 30.f);
            acc[nt][e] = l; mlo = fmaxf(mlo, l);
            float h = fminf(fmaxf(acc[nt][2+e]*invT, -30.f), 30.f);
            acc[nt][2+e] = h; mhi = fmaxf(mhi, h);
        }
    }
    mlo = fmaxf(mlo, __shfl_xor_sync(~0u, mlo, 1));
    mlo = fmaxf(mlo, __shfl_xor_sync(~0u, mlo, 2));
    mhi = fmaxf(mhi, __shfl_xor_sync(~0u, mhi, 1));
    mhi = fmaxf(mhi, __shfl_xor_sync(~0u, mhi, 2));
    float slo = 0.f, shi = 0.f;
    #pragma unroll
    for (int nt = 0; nt < 32; nt++) {
        #pragma unroll
        for (int e = 0; e < 2; e++) {
            float pl = __expf(acc[nt][e] - mlo);   acc[nt][e] = pl;   slo += pl;
            float ph = __expf(acc[nt][2+e] - mhi); acc[nt][2+e] = ph; shi += ph;
        }
    }
    slo += __shfl_xor_sync(~0u, slo, 1); slo += __shfl_xor_sync(~0u, slo, 2);
    shi += __shfl_xor_sync(~0u, shi, 1); shi += __shfl_xor_sync(~0u, shi, 2);
    float ilo = 1.f/slo, ihi = 1.f/shi;

    // P -> A fragments (C-frag layout == A-frag layout; k-tile kt = n-tiles 2kt,2kt+1)
    u32 pf[16][4];
    #pragma unroll
    for (int kt = 0; kt < 16; kt++) {
        pf[kt][0] = pack_bf2(acc[2*kt][0]*ilo,   acc[2*kt][1]*ilo);
        pf[kt][1] = pack_bf2(acc[2*kt][2]*ihi,   acc[2*kt][3]*ihi);
        pf[kt][2] = pack_bf2(acc[2*kt+1][0]*ilo, acc[2*kt+1][1]*ilo);
        pf[kt][3] = pack_bf2(acc[2*kt+1][2]*ihi, acc[2*kt+1][3]*ihi);
    }
    cpa_wait<0>();                     // V ready
    __syncthreads();

    {   // Phase 2: O = P @ V (B from Vs [p][d] via x4 trans)
        float oacc[16][4];
        #pragma unroll
        for (int nt = 0; nt < 16; nt++) { oacc[nt][0]=oacc[nt][1]=oacc[nt][2]=oacc[nt][3]=0.f; }
        u32 v_base = sm_u32(&Vs[((lane&7) + ((lane>>3)&1)*8)*XS_LD + ((lane>>4)&1)*8]);
        #pragma unroll
        for (int kt = 0; kt < 16; kt++) {
            #pragma unroll
            for (int ntp = 0; ntp < 8; ntp++) {
                u32 bf[4];
                ldsm_x4t(bf, v_base + (kt*16*XS_LD + ntp*16)*2);
                mma16816(oacc[2*ntp],   pf[kt], bf);
                mma16816(oacc[2*ntp+1], pf[kt], bf+2);
            }
        }
        size_t tok_lo = n0 + m_w + r, tok_hi = tok_lo + 8;
        #pragma unroll
        for (int nt = 0; nt < 16; nt++) {
            st_bf2(&g_ao[tok_lo*KD + nt*8 + col0], oacc[nt][0], oacc[nt][1]);
            st_bf2(&g_ao[tok_hi*KD + nt*8 + col0], oacc[nt][2], oacc[nt][3]);
        }
    }
}

// ---------------------------------------------------------------------------
// K4: y[c][hw] = ow[c][:] . ao[hw][:] + ob[c].  Tile 128c x 128hw, K=128.
// ---------------------------------------------------------------------------
#define OP_SMEM ((128*XS_LD + 128*XS_LD)*2)

__global__ __launch_bounds__(256,2) void oproj_mma(
    const float* __restrict__ ow, const float* __restrict__ ob)
{
    extern __shared__ __nv_bfloat16 smo[];
    __nv_bfloat16* OWs = smo;                 // [128c][136d]
    __nv_bfloat16* AOs = smo + 128*XS_LD;     // [128hw][136d]
    int tid = threadIdx.x;
    int c0 = blockIdx.x*128, hw0 = blockIdx.y*128, b = blockIdx.z;

    for (int i = tid; i < 128*16; i += 256) {
        int hw = i >> 4, d8 = (i & 15) << 3;
        cpa16(&AOs[hw*XS_LD + d8], &g_ao[((size_t)b*HWP + hw0 + hw)*KD + d8]);
    }
    cpa_commit();
    for (int i = tid; i < 128*32; i += 256) {
        int c = i >> 5, d4 = (i & 31) << 2;
        float4 v = *(const float4*)&ow[(size_t)(c0+c)*KD + d4];
        __nv_bfloat162* d2 = (__nv_bfloat162*)&OWs[c*XS_LD + d4];
        d2[0] = __floats2bfloat162_rn(v.x, v.y);
        d2[1] = __floats2bfloat162_rn(v.z, v.w);
    }
    cpa_wait<0>();
    __syncthreads();

    int warp = tid >> 5, lane = tid & 31;
    int c_w = warp*16;
    float acc[16][4];
    #pragma unroll
    for (int nt = 0; nt < 16; nt++) { acc[nt][0]=acc[nt][1]=acc[nt][2]=acc[nt][3]=0.f; }
    u32 a_base = sm_u32(&OWs[(c_w + (lane&15))*XS_LD + ((lane>>4)&1)*8]);
    u32 b_base = sm_u32(&AOs[((lane&7) + ((lane>>4)<<3))*XS_LD + ((lane>>3)&1)*8]);
    #pragma unroll
    for (int ks = 0; ks < 8; ks++) {
        u32 a[4];
        ldsm_x4(a, a_base + ks*16*2);
        #pragma unroll
        for (int ntp = 0; ntp < 8; ntp++) {
            u32 bf[4];
            ldsm_x4(bf, b_base + (ntp*16*XS_LD + ks*16)*2);
            mma16816(acc[2*ntp],   a, bf);
            mma16816(acc[2*ntp+1], a, bf+2);
        }
    }
    int r = lane >> 2, col0 = (lane & 3)*2;
    int c_lo = c0 + c_w + r, c_hi = c_lo + 8;
    float b_lo = __ldg(&ob[c_lo]), b_hi = __ldg(&ob[c_hi]);
    size_t base_lo = ((size_t)b*CC + c_lo)*HWP + hw0;
    size_t base_hi = ((size_t)b*CC + c_hi)*HWP + hw0;
    #pragma unroll
    for (int nt = 0; nt < 16; nt++) {
        st_bf2(&g_y[base_lo + nt*8 + col0], acc[nt][0]+b_lo, acc[nt][1]+b_lo);
        st_bf2(&g_y[base_hi + nt*8 + col0], acc[nt][2]+b_hi, acc[nt][3]+b_hi);
    }
}

// ---------------------------------------------------------------------------
// K5: depthwise 3x3 (SAME) on y (bf16), BN1, exact GELU, residual, gamma, BN2.
// ---------------------------------------------------------------------------
__global__ __launch_bounds__(256) void final_kernel(
    const float* __restrict__ x, const float* __restrict__ dww,
    const float* __restrict__ bn1w, const float* __restrict__ bn1b,
    const float* __restrict__ bn2w, const float* __restrict__ bn2b,
    const float* __restrict__ gamma, float* __restrict__ out)
{
    __shared__ float tile[10][34];
    int bc = blockIdx.z;
    int c = bc & (CC-1);
    int h0 = blockIdx.y*8, w0 = blockIdx.x*32;
    int tx = threadIdx.x, ty = threadIdx.y;
    const __nv_bfloat16* yp = g_y + (size_t)bc*HWP;
    int tid = ty*32 + tx;
    for (int i = tid; i < 34*10; i += 256) {
        int yy = i / 34, xx = i - yy*34;
        int gh = h0 + yy - 1, gw = w0 + xx - 1;
        float v = 0.f;
        if (gh >= 0 && gh < HH && gw >= 0 && gw < WWD)
            v = __bfloat162float(yp[gh*WWD + gw]);
        tile[yy][xx] = v;
    }
    __syncthreads();

    float kern[9];
    #pragma unroll
    for (int i = 0; i < 9; i++) kern[i] = dww[c*9 + i];
    float conv = 0.f;
    #pragma unroll
    for (int kh = 0; kh < 3; kh++) {
        #pragma unroll
        for (int kw = 0; kw < 3; kw++) conv += tile[ty+kh][tx+kw] * kern[kh*3+kw];
    }
    float inv = rsqrtf(1.f + BN_EPS);
    float z = conv * (bn1w[c]*inv) + bn1b[c];
    float gl = 0.5f * z * (1.f + erff(z * 0.70710678118654752f));
    float yv = tile[ty+1][tx+1];
    float ot = yv + gl;                           // out + local
    int hw = (h0+ty)*WWD + (w0+tx);
    float xv = x[(size_t)bc*HWP + hw];
    out[(size_t)bc*HWP + hw] = (xv + gamma[c]*ot) * (bn2w[c]*inv) + bn2b[c];
}

// ---------------------------------------------------------------------------
extern "C" void kernel_launch(void* const* d_in, const int* in_sizes, int n_in,
                              void* d_out, int out_size)
{
    (void)in_sizes; (void)n_in; (void)out_size;
    const float* x    = (const float*)d_in[0];
    const float* m    = (const float*)d_in[1];
    const float* qw   = (const float*)d_in[2];
    const float* qb   = (const float*)d_in[3];
    const float* kw   = (const float*)d_in[4];
    const float* kb   = (const float*)d_in[5];
    const float* vw   = (const float*)d_in[6];
    const float* vb   = (const float*)d_in[7];
    const float* ow   = (const float*)d_in[8];
    const float* ob   = (const float*)d_in[9];
    const float* dww  = (const float*)d_in[10];
    const float* bn1w = (const float*)d_in[11];
    const float* bn1b = (const float*)d_in[12];
    const float* bn2w = (const float*)d_in[13];
    const float* bn2b = (const float*)d_in[14];
    const float* gam  = (const float*)d_in[15];
    float* out = (float*)d_out;

    cudaFuncSetAttribute(qproj_mma, cudaFuncAttributeMaxDynamicSharedMemorySize, QP_SMEM);
    cudaFuncSetAttribute(attn_mma,  cudaFuncAttributeMaxDynamicSharedMemorySize, AT_SMEM);
    cudaFuncSetAttribute(oproj_mma, cudaFuncAttributeMaxDynamicSharedMemorySize, OP_SMEM);

    kv_kernel<<<PP, KD>>>(m, kw, kb, vw, vb);
    qproj_mma<<<dim3(HWP/128, BB), 256, QP_SMEM>>>(x, qw, qb);
    attn_mma<<<NTOK/128, 256, AT_SMEM>>>();
    oproj_mma<<<dim3(CC/128, HWP/128, BB), 256, OP_SMEM>>>(ow, ob);
    final_kernel<<<dim3(WWD/32, HH/8, BB*CC), dim3(32,8)>>>(
        x, dww, bn1w, bn1b, bn2w, bn2b, gam, out);
}

// round 8
// speedup vs baseline: 2.6406x; 1.0072x over previous
#include <cuda_runtime.h>
#include <cuda_bf16.h>
#include <math.h>

typedef unsigned int u32;

// Problem constants
#define BB   16
#define CC   256
#define HH   64
#define WWD  64
#define HWP  (HH*WWD)          // 4096
#define NTOK (BB*HWP)          // 65536
#define KD   128
#define PP   256
#define BN_EPS 1e-5f

// Scratch (device globals: allocation-free per harness rules)
__device__ __align__(256) __nv_bfloat16 g_k[PP*KD];
__device__ __align__(256) __nv_bfloat16 g_v[PP*KD];
__device__ __align__(256) __nv_bfloat16 g_q[(size_t)NTOK*KD];    // 16 MB
__device__ __align__(256) __nv_bfloat16 g_ao[(size_t)NTOK*KD];   // 16 MB
__device__ __align__(256) __nv_bfloat16 g_y[(size_t)BB*CC*HWP];  // 32 MB

// ---------------------------------------------------------------------------
// MMA / ldmatrix helpers (m16n8k16 bf16, fp32 accum)
// ---------------------------------------------------------------------------
__device__ __forceinline__ u32 sm_u32(const void* p) {
    return (u32)__cvta_generic_to_shared(p);
}
__device__ __forceinline__ void ldsm_x4(u32* r, u32 a) {
    asm volatile("ldmatrix.sync.aligned.m8n8.x4.shared.b16 {%0,%1,%2,%3},[%4];"
                 : "=r"(r[0]),"=r"(r[1]),"=r"(r[2]),"=r"(r[3]) : "r"(a));
}
__device__ __forceinline__ void ldsm_x4t(u32* r, u32 a) {
    asm volatile("ldmatrix.sync.aligned.m8n8.x4.trans.shared.b16 {%0,%1,%2,%3},[%4];"
                 : "=r"(r[0]),"=r"(r[1]),"=r"(r[2]),"=r"(r[3]) : "r"(a));
}
__device__ __forceinline__ void mma16816(float* d, const u32* a, const u32* b) {
    asm volatile("mma.sync.aligned.m16n8k16.row.col.f32.bf16.bf16.f32 "
                 "{%0,%1,%2,%3},{%4,%5,%6,%7},{%8,%9},{%0,%1,%2,%3};"
                 : "+f"(d[0]),"+f"(d[1]),"+f"(d[2]),"+f"(d[3])
                 : "r"(a[0]),"r"(a[1]),"r"(a[2]),"r"(a[3]),"r"(b[0]),"r"(b[1]));
}
__device__ __forceinline__ void st_bf2(__nv_bfloat16* p, float a, float b) {
    *(__nv_bfloat162*)p = __floats2bfloat162_rn(a, b);
}
__device__ __forceinline__ u32 pack_bf2(float a, float b) {
    __nv_bfloat162 t = __floats2bfloat162_rn(a, b);
    return *(u32*)&t;
}
__device__ __forceinline__ void cpa16(void* dst, const void* src) {
    u32 d = sm_u32(dst);
    asm volatile("cp.async.cg.shared.global [%0], [%1], 16;" :: "r"(d), "l"(src));
}
__device__ __forceinline__ void cpa_commit() {
    asm volatile("cp.async.commit_group;");
}
template<int N> __device__ __forceinline__ void cpa_wait() {
    asm volatile("cp.async.wait_group %0;" :: "n"(N));
}

// ---------------------------------------------------------------------------
// K1: k = l2norm(m @ k_w^T + k_b), v = m @ v_w^T + v_b  (tiny, fp32 math)
// ---------------------------------------------------------------------------
__global__ __launch_bounds__(128) void kv_kernel(
    const float* __restrict__ m, const float* __restrict__ kw,
    const float* __restrict__ kb, const float* __restrict__ vw,
    const float* __restrict__ vb)
{
    __shared__ float mrow[KD];
    __shared__ float red[KD];
    int p = blockIdx.x;
    int d = threadIdx.x;
    mrow[d] = m[p*KD + d];
    __syncthreads();
    float kkv = kb[d], vvv = vb[d];
    #pragma unroll 4
    for (int j = 0; j < KD; j++) {
        float mj = mrow[j];
        kkv += mj * kw[d*KD + j];
        vvv += mj * vw[d*KD + j];
    }
    red[d] = kkv*kkv;
    __syncthreads();
    for (int s = 64; s > 0; s >>= 1) {
        if (d < s) red[d] += red[d+s];
        __syncthreads();
    }
    float scale = 1.f / fmaxf(sqrtf(red[0]), 1e-12f);
    g_k[p*KD + d] = __float2bfloat16(kkv * scale);
    g_v[p*KD + d] = __float2bfloat16(vvv);
}

// ---------------------------------------------------------------------------
// K2: qproj + L2 norm. Tile: 128 pixels x 128 dims, K=256 channels.
// Xs[c][m] col-major A (x4t), Qw[d][c] = [n][k] B (x4). Pipelined frags.
// ---------------------------------------------------------------------------
#define XS_LD 136
#define QW_LD 264
#define QP_SMEM ((256*XS_LD + 128*QW_LD)*2)

__global__ __launch_bounds__(256,1) void qproj_mma(
    const float* __restrict__ x, const float* __restrict__ qw,
    const float* __restrict__ qb)
{
    extern __shared__ __nv_bfloat16 smq[];
    __nv_bfloat16* Xs = smq;                 // [256][XS_LD]
    __nv_bfloat16* Qw = smq + 256*XS_LD;     // [128][QW_LD]
    int tid = threadIdx.x;
    int b = blockIdx.y, hw0 = blockIdx.x*128;
    const float* xb = x + (size_t)b*CC*HWP;

    for (int i = tid; i < 256*32; i += 256) {           // X: 256c x 128m
        int c = i >> 5, m4 = (i & 31) << 2;
        float4 v = *(const float4*)&xb[(size_t)c*HWP + hw0 + m4];
        __nv_bfloat162* d2 = (__nv_bfloat162*)&Xs[c*XS_LD + m4];
        d2[0] = __floats2bfloat162_rn(v.x, v.y);
        d2[1] = __floats2bfloat162_rn(v.z, v.w);
    }
    for (int i = tid; i < 128*64; i += 256) {           // QW: 128d x 256c
        int d = i >> 6, c4 = (i & 63) << 2;
        float4 v = *(const float4*)&qw[d*CC + c4];
        __nv_bfloat162* d2 = (__nv_bfloat162*)&Qw[d*QW_LD + c4];
        d2[0] = __floats2bfloat162_rn(v.x, v.y);
        d2[1] = __floats2bfloat162_rn(v.z, v.w);
    }
    __syncthreads();

    int warp = tid >> 5, lane = tid & 31;
    int m_w = warp*16;
    float acc[16][4];
    #pragma unroll
    for (int nt = 0; nt < 16; nt++) { acc[nt][0]=acc[nt][1]=acc[nt][2]=acc[nt][3]=0.f; }

    u32 a_base = sm_u32(&Xs[((lane&7) + ((lane>>4)<<3))*XS_LD + m_w + ((lane>>3)&1)*8]);
    u32 b_base = sm_u32(&Qw[((lane&7) + ((lane>>4)<<3))*QW_LD + ((lane>>3)&1)*8]);
    u32 a[2][4], bf[2][4];
    ldsm_x4t(a[0], a_base);
    ldsm_x4(bf[0], b_base);
    #pragma unroll
    for (int ks = 0; ks < 16; ks++) {
        if (ks < 15) ldsm_x4t(a[(ks+1)&1], a_base + (ks+1)*16*XS_LD*2);
        #pragma unroll
        for (int ntp = 0; ntp < 8; ntp++) {
            int nk = ks, nn = ntp+1;
            if (nn == 8) { nn = 0; nk++; }
            if (nk < 16) ldsm_x4(bf[(ntp+1)&1], b_base + (nn*16*QW_LD + nk*16)*2);
            mma16816(acc[2*ntp],   a[ks&1], bf[ntp&1]);
            mma16816(acc[2*ntp+1], a[ks&1], bf[ntp&1]+2);
        }
    }
    // bias + L2 norm (row spread over lane quads) + bf16 store
    int r = lane >> 2, col0 = (lane & 3)*2;
    float slo = 0.f, shi = 0.f;
    #pragma unroll
    for (int nt = 0; nt < 16; nt++) {
        float b0 = __ldg(&qb[nt*8+col0]), b1 = __ldg(&qb[nt*8+col0+1]);
        acc[nt][0] += b0; acc[nt][1] += b1; acc[nt][2] += b0; acc[nt][3] += b1;
        slo += acc[nt][0]*acc[nt][0] + acc[nt][1]*acc[nt][1];
        shi += acc[nt][2]*acc[nt][2] + acc[nt][3]*acc[nt][3];
    }
    slo += __shfl_xor_sync(~0u, slo, 1); slo += __shfl_xor_sync(~0u, slo, 2);
    shi += __shfl_xor_sync(~0u, shi, 1); shi += __shfl_xor_sync(~0u, shi, 2);
    float s_lo = 1.f/fmaxf(sqrtf(slo), 1e-12f);
    float s_hi = 1.f/fmaxf(sqrtf(shi), 1e-12f);
    size_t tok_lo = (size_t)b*HWP + hw0 + m_w + r;
    size_t tok_hi = tok_lo + 8;
    #pragma unroll
    for (int nt = 0; nt < 16; nt++) {
        st_bf2(&g_q[tok_lo*KD + nt*8 + col0], acc[nt][0]*s_lo, acc[nt][1]*s_lo);
        st_bf2(&g_q[tok_hi*KD + nt*8 + col0], acc[nt][2]*s_hi, acc[nt][3]*s_hi);
    }
}

// ---------------------------------------------------------------------------
// K3: fused attention, 128 tokens/CTA. S=Q@K^T -> clipped exp (no max sub,
// safe since logits in [-30,30]) -> P in registers -> O=P@V. Pipelined frags.
// ---------------------------------------------------------------------------
#define AT_SMEM ((256*XS_LD + 128*XS_LD + 256*XS_LD)*2)   // 174080 B

__global__ __launch_bounds__(256,1) void attn_mma()
{
    extern __shared__ __nv_bfloat16 sma[];
    __nv_bfloat16* Ks = sma;                               // [256][136]
    __nv_bfloat16* Qs = sma + 256*XS_LD;                   // [128][136]
    __nv_bfloat16* Vs = sma + 256*XS_LD + 128*XS_LD;       // [256][136]
    int tid = threadIdx.x;
    size_t n0 = (size_t)blockIdx.x * 128;
    int warp = tid >> 5, lane = tid & 31;
    int m_w = warp*16;
    int r = lane >> 2, col0 = (lane & 3)*2;

    for (int i = tid; i < 128*16; i += 256) {
        int m = i >> 4, d8 = (i & 15) << 3;
        cpa16(&Qs[m*XS_LD + d8], &g_q[(n0+m)*KD + d8]);
    }
    for (int i = tid; i < 256*16; i += 256) {
        int p = i >> 4, d8 = (i & 15) << 3;
        cpa16(&Ks[p*XS_LD + d8], &g_k[p*KD + d8]);
    }
    cpa_commit();                      // group A: Q+K
    for (int i = tid; i < 256*16; i += 256) {
        int p = i >> 4, d8 = (i & 15) << 3;
        cpa16(&Vs[p*XS_LD + d8], &g_v[p*KD + d8]);
    }
    cpa_commit();                      // group B: V (overlaps phase 1)
    cpa_wait<1>();                     // Q+K ready
    __syncthreads();

    float acc[32][4];
    #pragma unroll
    for (int nt = 0; nt < 32; nt++) { acc[nt][0]=acc[nt][1]=acc[nt][2]=acc[nt][3]=0.f; }
    {   // Phase 1: S = Q @ K^T (pipelined)
        u32 a_base = sm_u32(&Qs[(m_w + (lane&15))*XS_LD + ((lane>>4)&1)*8]);
        u32 b_base = sm_u32(&Ks[((lane&7) + ((lane>>4)<<3))*XS_LD + ((lane>>3)&1)*8]);
        u32 a[2][4], bf[2][4];
        ldsm_x4(a[0], a_base);
        ldsm_x4(bf[0], b_base);
        #pragma unroll
        for (int ks = 0; ks < 8; ks++) {
            if (ks < 7) ldsm_x4(a[(ks+1)&1], a_base + (ks+1)*16*2);
            #pragma unroll
            for (int ntp = 0; ntp < 16; ntp++) {
                int nk = ks, nn = ntp+1;
                if (nn == 16) { nn = 0; nk++; }
                if (nk < 8) ldsm_x4(bf[(ntp+1)&1], b_base + (nn*16*XS_LD + nk*16)*2);
                mma16816(acc[2*ntp],   a[ks&1], bf[ntp&1]);
                mma16816(acc[2*ntp+1], a[ks&1], bf[ntp&1]+2);
            }
        }
    }
    // clipped softmax WITHOUT max subtraction (logits bounded in [-30,30])
    const float invT = 1.0f/0.07f;
    float slo = 0.f, shi = 0.f;
    #pragma unroll
    for (int nt = 0; nt < 32; nt++) {
        #pragma unroll
        for (int e = 0; e < 2; e++) {
            float pl = __expf(fminf(fmaxf(acc[nt][e]*invT,   -30.f), 30.f));
            float ph = __expf(fminf(fmaxf(acc[nt][2+e]*invT, -30.f), 30.f));
            acc[nt][e] = pl;   slo += pl;
            acc[nt][2+e] = ph; shi += ph;
        }
    }
    slo += __shfl_xor_sync(~0u, slo, 1); slo += __shfl_xor_sync(~0u, slo, 2);
    shi += __shfl_xor_sync(~0u, shi, 1); shi += __shfl_xor_sync(~0u, shi, 2);
    float ilo = 1.f/slo, ihi = 1.f/shi;

    // P -> A fragments (C-frag layout == A-frag layout; k-tile kt = n-tiles 2kt,2kt+1)
    u32 pf[16][4];
    #pragma unroll
    for (int kt = 0; kt < 16; kt++) {
        pf[kt][0] = pack_bf2(acc[2*kt][0]*ilo,   acc[2*kt][1]*ilo);
        pf[kt][1] = pack_bf2(acc[2*kt][2]*ihi,   acc[2*kt][3]*ihi);
        pf[kt][2] = pack_bf2(acc[2*kt+1][0]*ilo, acc[2*kt+1][1]*ilo);
        pf[kt][3] = pack_bf2(acc[2*kt+1][2]*ihi, acc[2*kt+1][3]*ihi);
    }
    cpa_wait<0>();                     // V ready
    __syncthreads();

    {   // Phase 2: O = P @ V (B from Vs [p][d] via x4 trans, pipelined)
        float oacc[16][4];
        #pragma unroll
        for (int nt = 0; nt < 16; nt++) { oacc[nt][0]=oacc[nt][1]=oacc[nt][2]=oacc[nt][3]=0.f; }
        u32 v_base = sm_u32(&Vs[((lane&7) + ((lane>>3)&1)*8)*XS_LD + ((lane>>4)&1)*8]);
        u32 bf[2][4];
        ldsm_x4t(bf[0], v_base);
        #pragma unroll
        for (int kt = 0; kt < 16; kt++) {
            #pragma unroll
            for (int ntp = 0; ntp < 8; ntp++) {
                int nk = kt, nn = ntp+1;
                if (nn == 8) { nn = 0; nk++; }
                if (nk < 16) ldsm_x4t(bf[(ntp+1)&1], v_base + (nk*16*XS_LD + nn*16)*2);
                mma16816(oacc[2*ntp],   pf[kt], bf[ntp&1]);
                mma16816(oacc[2*ntp+1], pf[kt], bf[ntp&1]+2);
            }
        }
        size_t tok_lo = n0 + m_w + r, tok_hi = tok_lo + 8;
        #pragma unroll
        for (int nt = 0; nt < 16; nt++) {
            st_bf2(&g_ao[tok_lo*KD + nt*8 + col0], oacc[nt][0], oacc[nt][1]);
            st_bf2(&g_ao[tok_hi*KD + nt*8 + col0], oacc[nt][2], oacc[nt][3]);
        }
    }
}

// ---------------------------------------------------------------------------
// K4: y[c][hw] = ow[c][:] . ao[hw][:] + ob[c].  Tile 128c x 128hw, K=128.
// ---------------------------------------------------------------------------
#define OP_SMEM ((128*XS_LD + 128*XS_LD)*2)

__global__ __launch_bounds__(256,2) void oproj_mma(
    const float* __restrict__ ow, const float* __restrict__ ob)
{
    extern __shared__ __nv_bfloat16 smo[];
    __nv_bfloat16* OWs = smo;                 // [128c][136d]
    __nv_bfloat16* AOs = smo + 128*XS_LD;     // [128hw][136d]
    int tid = threadIdx.x;
    int c0 = blockIdx.x*128, hw0 = blockIdx.y*128, b = blockIdx.z;

    for (int i = tid; i < 128*16; i += 256) {
        int hw = i >> 4, d8 = (i & 15) << 3;
        cpa16(&AOs[hw*XS_LD + d8], &g_ao[((size_t)b*HWP + hw0 + hw)*KD + d8]);
    }
    cpa_commit();
    for (int i = tid; i < 128*32; i += 256) {
        int c = i >> 5, d4 = (i & 31) << 2;
        float4 v = *(const float4*)&ow[(size_t)(c0+c)*KD + d4];
        __nv_bfloat162* d2 = (__nv_bfloat162*)&OWs[c*XS_LD + d4];
        d2[0] = __floats2bfloat162_rn(v.x, v.y);
        d2[1] = __floats2bfloat162_rn(v.z, v.w);
    }
    cpa_wait<0>();
    __syncthreads();

    int warp = tid >> 5, lane = tid & 31;
    int c_w = warp*16;
    float acc[16][4];
    #pragma unroll
    for (int nt = 0; nt < 16; nt++) { acc[nt][0]=acc[nt][1]=acc[nt][2]=acc[nt][3]=0.f; }
    u32 a_base = sm_u32(&OWs[(c_w + (lane&15))*XS_LD + ((lane>>4)&1)*8]);
    u32 b_base = sm_u32(&AOs[((lane&7) + ((lane>>4)<<3))*XS_LD + ((lane>>3)&1)*8]);
    u32 a[2][4], bf[2][4];
    ldsm_x4(a[0], a_base);
    ldsm_x4(bf[0], b_base);
    #pragma unroll
    for (int ks = 0; ks < 8; ks++) {
        if (ks < 7) ldsm_x4(a[(ks+1)&1], a_base + (ks+1)*16*2);
        #pragma unroll
        for (int ntp = 0; ntp < 8; ntp++) {
            int nk = ks, nn = ntp+1;
            if (nn == 8) { nn = 0; nk++; }
            if (nk < 8) ldsm_x4(bf[(ntp+1)&1], b_base + (nn*16*XS_LD + nk*16)*2);
            mma16816(acc[2*ntp],   a[ks&1], bf[ntp&1]);
            mma16816(acc[2*ntp+1], a[ks&1], bf[ntp&1]+2);
        }
    }
    int r = lane >> 2, col0 = (lane & 3)*2;
    int c_lo = c0 + c_w + r, c_hi = c_lo + 8;
    float b_lo = __ldg(&ob[c_lo]), b_hi = __ldg(&ob[c_hi]);
    size_t base_lo = ((size_t)b*CC + c_lo)*HWP + hw0;
    size_t base_hi = ((size_t)b*CC + c_hi)*HWP + hw0;
    #pragma unroll
    for (int nt = 0; nt < 16; nt++) {
        st_bf2(&g_y[base_lo + nt*8 + col0], acc[nt][0]+b_lo, acc[nt][1]+b_lo);
        st_bf2(&g_y[base_hi + nt*8 + col0], acc[nt][2]+b_hi, acc[nt][3]+b_hi);
    }
}

// ---------------------------------------------------------------------------
// K5: depthwise 3x3 (SAME) on y (bf16), BN1, exact GELU, residual, gamma, BN2.
// ---------------------------------------------------------------------------
__global__ __launch_bounds__(256) void final_kernel(
    const float* __restrict__ x, const float* __restrict__ dww,
    const float* __restrict__ bn1w, const float* __restrict__ bn1b,
    const float* __restrict__ bn2w, const float* __restrict__ bn2b,
    const float* __restrict__ gamma, float* __restrict__ out)
{
    __shared__ float tile[10][34];
    int bc = blockIdx.z;
    int c = bc & (CC-1);
    int h0 = blockIdx.y*8, w0 = blockIdx.x*32;
    int tx = threadIdx.x, ty = threadIdx.y;
    const __nv_bfloat16* yp = g_y + (size_t)bc*HWP;
    int tid = ty*32 + tx;
    for (int i = tid; i < 34*10; i += 256) {
        int yy = i / 34, xx = i - yy*34;
        int gh = h0 + yy - 1, gw = w0 + xx - 1;
        float v = 0.f;
        if (gh >= 0 && gh < HH && gw >= 0 && gw < WWD)
            v = __bfloat162float(yp[gh*WWD + gw]);
        tile[yy][xx] = v;
    }
    __syncthreads();

    float kern[9];
    #pragma unroll
    for (int i = 0; i < 9; i++) kern[i] = dww[c*9 + i];
    float conv = 0.f;
    #pragma unroll
    for (int kh = 0; kh < 3; kh++) {
        #pragma unroll
        for (int kw = 0; kw < 3; kw++) conv += tile[ty+kh][tx+kw] * kern[kh*3+kw];
    }
    float inv = rsqrtf(1.f + BN_EPS);
    float z = conv * (bn1w[c]*inv) + bn1b[c];
    float gl = 0.5f * z * (1.f + erff(z * 0.70710678118654752f));
    float yv = tile[ty+1][tx+1];
    float ot = yv + gl;                           // out + local
    int hw = (h0+ty)*WWD + (w0+tx);
    float xv = x[(size_t)bc*HWP + hw];
    out[(size_t)bc*HWP + hw] = (xv + gamma[c]*ot) * (bn2w[c]*inv) + bn2b[c];
}

// ---------------------------------------------------------------------------
extern "C" void kernel_launch(void* const* d_in, const int* in_sizes, int n_in,
                              void* d_out, int out_size)
{
    (void)in_sizes; (void)n_in; (void)out_size;
    const float* x    = (const float*)d_in[0];
    const float* m    = (const float*)d_in[1];
    const float* qw   = (const float*)d_in[2];
    const float* qb   = (const float*)d_in[3];
    const float* kw   = (const float*)d_in[4];
    const float* kb   = (const float*)d_in[5];
    const float* vw   = (const float*)d_in[6];
    const float* vb   = (const float*)d_in[7];
    const float* ow   = (const float*)d_in[8];
    const float* ob   = (const float*)d_in[9];
    const float* dww  = (const float*)d_in[10];
    const float* bn1w = (const float*)d_in[11];
    const float* bn1b = (const float*)d_in[12];
    const float* bn2w = (const float*)d_in[13];
    const float* bn2b = (const float*)d_in[14];
    const float* gam  = (const float*)d_in[15];
    float* out = (float*)d_out;

    cudaFuncSetAttribute(qproj_mma, cudaFuncAttributeMaxDynamicSharedMemorySize, QP_SMEM);
    cudaFuncSetAttribute(attn_mma,  cudaFuncAttributeMaxDynamicSharedMemorySize, AT_SMEM);
    cudaFuncSetAttribute(oproj_mma, cudaFuncAttributeMaxDynamicSharedMemorySize, OP_SMEM);

    kv_kernel<<<PP, KD>>>(m, kw, kb, vw, vb);
    qproj_mma<<<dim3(HWP/128, BB), 256, QP_SMEM>>>(x, qw, qb);
    attn_mma<<<NTOK/128, 256, AT_SMEM>>>();
    oproj_mma<<<dim3(CC/128, HWP/128, BB), 256, OP_SMEM>>>(ow, ob);
    final_kernel<<<dim3(WWD/32, HH/8, BB*CC), dim3(32,8)>>>(
        x, dww, bn1w, bn1b, bn2w, bn2b, gam, out);
}